// round 4
// baseline (speedup 1.0000x reference)
#include <cuda_runtime.h>
#include <cuda_bf16.h>
#include <cstdint>

// Problem constants
#define BATCH 512
#define SEQ   256
#define CEMB  384
#define HEAD  64
#define SCALE 0.125f   // 64^-0.5

// Scratch: Q, K, V projections [B*T, H]  (device globals — allowed scratch)
__device__ float g_Q[(size_t)BATCH * SEQ * HEAD];
__device__ float g_K[(size_t)BATCH * SEQ * HEAD];
__device__ float g_V[(size_t)BATCH * SEQ * HEAD];

// ---------------------------------------------------------------------------
// packed f32x2 helpers (Blackwell FFMA2 path — 2x fp32 throughput vs FFMA)
// ---------------------------------------------------------------------------
__device__ __forceinline__ void fma2(unsigned long long& d,
                                     unsigned long long a,
                                     unsigned long long b) {
    asm("fma.rn.f32x2 %0, %1, %2, %0;" : "+l"(d) : "l"(a), "l"(b));
}
__device__ __forceinline__ unsigned long long pack2(float v) {
    unsigned long long r;
    asm("mov.b64 %0, {%1, %1};" : "=l"(r) : "f"(v));
    return r;
}
union F2U { unsigned long long u; float2 f; };

// ---------------------------------------------------------------------------
// Kernel 1: fused QKV projection.
//   out[m, n] = sum_c x[m, c] * W[c, n] + bias[n]
//   M = B*T = 131072, Kdim = 384, N = 64 per weight; blockIdx.y selects Q/K/V.
//   Tile: 128 (M) x 64 (N), BK = 16, 256 threads, 8x4 outputs/thread via f32x2.
// ---------------------------------------------------------------------------
__global__ __launch_bounds__(256)
void qkv_kernel(const float* __restrict__ x,
                const float* __restrict__ Wq, const float* __restrict__ bq,
                const float* __restrict__ Wk, const float* __restrict__ bk,
                const float* __restrict__ Wv, const float* __restrict__ bv) {
    const int nt = blockIdx.y;
    const float* __restrict__ W    = (nt == 0) ? Wq : (nt == 1) ? Wk : Wv;
    const float* __restrict__ bias = (nt == 0) ? bq : (nt == 1) ? bk : bv;
    float* __restrict__ out        = (nt == 0) ? g_Q : (nt == 1) ? g_K : g_V;

    __shared__ float As[16][132];   // A^T tile: As[k][m], pad->2-way max on store
    __shared__ float Bs2[16][128];  // B tile with each value DUPLICATED: [k][2n],[2n+1]

    const int tid = threadIdx.x;
    const int ty = tid >> 4;   // 0..15 : row group (8 rows each)
    const int tx = tid & 15;   // 0..15 : col group (4 cols each)
    const int m0 = blockIdx.x * 128;

    unsigned long long acc[4][4];   // acc[p][j] = rows (ty*8+2p, +1), col tx*4+j
    #pragma unroll
    for (int p = 0; p < 4; ++p)
        #pragma unroll
        for (int j = 0; j < 4; ++j) acc[p][j] = 0ull;

    for (int kb = 0; kb < CEMB; kb += 16) {
        // Load A tile (128 x 16), store transposed
        #pragma unroll
        for (int it = 0; it < 2; ++it) {
            int idx = tid + it * 256;          // 0..511 float4s
            int row = idx >> 2;
            int c   = idx & 3;
            float4 v = *(const float4*)(x + (size_t)(m0 + row) * CEMB + kb + c * 4);
            As[c * 4 + 0][row] = v.x;
            As[c * 4 + 1][row] = v.y;
            As[c * 4 + 2][row] = v.z;
            As[c * 4 + 3][row] = v.w;
        }
        // Load W tile (16 x 64), duplicated per value for f32x2
        #pragma unroll
        for (int it = 0; it < 4; ++it) {
            int idx = tid + it * 256;          // 0..1023
            int kk = idx >> 6;
            int n  = idx & 63;
            float v = W[(size_t)(kb + kk) * HEAD + n];
            Bs2[kk][2 * n]     = v;
            Bs2[kk][2 * n + 1] = v;
        }
        __syncthreads();

        #pragma unroll
        for (int k = 0; k < 16; ++k) {
            ulonglong2 a01 = *(const ulonglong2*)(&As[k][ty * 8]);
            ulonglong2 a23 = *(const ulonglong2*)(&As[k][ty * 8 + 4]);
            ulonglong2 b01 = *(const ulonglong2*)(&Bs2[k][tx * 8]);
            ulonglong2 b23 = *(const ulonglong2*)(&Bs2[k][tx * 8 + 4]);
            fma2(acc[0][0], a01.x, b01.x); fma2(acc[0][1], a01.x, b01.y);
            fma2(acc[0][2], a01.x, b23.x); fma2(acc[0][3], a01.x, b23.y);
            fma2(acc[1][0], a01.y, b01.x); fma2(acc[1][1], a01.y, b01.y);
            fma2(acc[1][2], a01.y, b23.x); fma2(acc[1][3], a01.y, b23.y);
            fma2(acc[2][0], a23.x, b01.x); fma2(acc[2][1], a23.x, b01.y);
            fma2(acc[2][2], a23.x, b23.x); fma2(acc[2][3], a23.x, b23.y);
            fma2(acc[3][0], a23.y, b01.x); fma2(acc[3][1], a23.y, b01.y);
            fma2(acc[3][2], a23.y, b23.x); fma2(acc[3][3], a23.y, b23.y);
        }
        __syncthreads();
    }

    float4 b4 = *(const float4*)(bias + tx * 4);
    #pragma unroll
    for (int p = 0; p < 4; ++p) {
        F2U u0, u1, u2, u3;
        u0.u = acc[p][0]; u1.u = acc[p][1]; u2.u = acc[p][2]; u3.u = acc[p][3];
        int row0 = m0 + ty * 8 + 2 * p;
        float4 r0 = make_float4(u0.f.x + b4.x, u1.f.x + b4.y, u2.f.x + b4.z, u3.f.x + b4.w);
        float4 r1 = make_float4(u0.f.y + b4.x, u1.f.y + b4.y, u2.f.y + b4.z, u3.f.y + b4.w);
        *(float4*)(out + (size_t)row0 * HEAD + tx * 4)       = r0;
        *(float4*)(out + (size_t)(row0 + 1) * HEAD + tx * 4) = r1;
    }
}

// ---------------------------------------------------------------------------
// Kernel 2: causal attention per (batch, 64-query tile).
//   grid = (4, 512), 256 threads.
//   Phase 1: S = (Q*SCALE) K^T over kt<=qt tiles   -> sS (64 x 256, fp32)
//   Softmax: row max/exp/sum (unnormalized; divide deferred to epilogue)
//   Phase 2: O = P V, divide by row sum, store.
// SMEM (floats):
//   sQ  [64][132]  Q^T, each value DUPLICATED along q (for f32x2)   8448
//   sKV [64][68]   K^T tile (phase 1) reused as V tile (phase 2)    4352
//   sS  [64][256]  scores / probs                                  16384
//   redm[256] reds[256] rsum[64]                                     576
// Total 29760 floats = 119040 B dynamic.
// ---------------------------------------------------------------------------
#define ATTN_SMEM_FLOATS (8448 + 4352 + 16384 + 256 + 256 + 64)
#define ATTN_SMEM_BYTES  (ATTN_SMEM_FLOATS * 4)

__global__ __launch_bounds__(256)
void attn_kernel(float* __restrict__ outp) {
    extern __shared__ float sm[];
    float* sQ   = sm;               // [h][2q] duplicated
    float* sKV  = sQ + 8448;        // phase1: [h][k] (K^T) ; phase2: [k][h] (V)
    float* sS   = sKV + 4352;       // [q][256]
    float* redm = sS + 16384;       // [64][4]
    float* reds = redm + 256;       // [64][4]
    float* rsum = reds + 256;       // [64]

    const int tid = threadIdx.x;
    const int ty = tid >> 4;        // 0..15
    const int tx = tid & 15;        // 0..15
    const int b  = blockIdx.y;
    const int qt = blockIdx.x;      // 0..3
    const int r0 = qt * 64;

    const float* __restrict__ Qg = g_Q + ((size_t)b * SEQ + r0) * HEAD;

    // Load Q tile transposed + scaled + duplicated: sQ[h*132 + 2q] = sQ[.. +1] = Q[q][h]*SCALE
    for (int idx = tid; idx < 1024; idx += 256) {
        int q  = idx >> 4;
        int hq = idx & 15;
        float4 v = *(const float4*)(Qg + (size_t)q * HEAD + hq * 4);
        float vv[4] = {v.x * SCALE, v.y * SCALE, v.z * SCALE, v.w * SCALE};
        #pragma unroll
        for (int u = 0; u < 4; ++u) {
            int h = hq * 4 + u;
            sQ[h * 132 + 2 * q]     = vv[u];
            sQ[h * 132 + 2 * q + 1] = vv[u];
        }
    }
    __syncthreads();

    // ---------------- Phase 1: scores ----------------
    for (int kt = 0; kt <= qt; ++kt) {
        const float* __restrict__ Kg = g_K + ((size_t)b * SEQ + kt * 64) * HEAD;
        // Load K tile transposed: sKV[h*68 + k] = K[k][h]
        for (int idx = tid; idx < 1024; idx += 256) {
            int k  = idx >> 4;
            int hq = idx & 15;
            float4 v = *(const float4*)(Kg + (size_t)k * HEAD + hq * 4);
            sKV[(hq * 4 + 0) * 68 + k] = v.x;
            sKV[(hq * 4 + 1) * 68 + k] = v.y;
            sKV[(hq * 4 + 2) * 68 + k] = v.z;
            sKV[(hq * 4 + 3) * 68 + k] = v.w;
        }
        __syncthreads();

        unsigned long long accS[4][2];   // [q 0..3][k-pair 0..1]
        #pragma unroll
        for (int i = 0; i < 4; ++i) { accS[i][0] = 0ull; accS[i][1] = 0ull; }

        #pragma unroll 4
        for (int h = 0; h < 64; ++h) {
            ulonglong2 a01 = *(const ulonglong2*)(&sQ[h * 132 + ty * 8]);      // (q0,q0),(q1,q1)
            ulonglong2 a23 = *(const ulonglong2*)(&sQ[h * 132 + ty * 8 + 4]);  // (q2,q2),(q3,q3)
            ulonglong2 bk  = *(const ulonglong2*)(&sKV[h * 68 + tx * 4]);      // (k0,k1),(k2,k3)
            fma2(accS[0][0], a01.x, bk.x); fma2(accS[0][1], a01.x, bk.y);
            fma2(accS[1][0], a01.y, bk.x); fma2(accS[1][1], a01.y, bk.y);
            fma2(accS[2][0], a23.x, bk.x); fma2(accS[2][1], a23.x, bk.y);
            fma2(accS[3][0], a23.y, bk.x); fma2(accS[3][1], a23.y, bk.y);
        }

        // Write (with causal mask on the diagonal tile)
        #pragma unroll
        for (int i = 0; i < 4; ++i) {
            F2U u0, u1; u0.u = accS[i][0]; u1.u = accS[i][1];
            float4 sv = make_float4(u0.f.x, u0.f.y, u1.f.x, u1.f.y);
            if (kt == qt) {
                int ql = ty * 4 + i;
                if (tx * 4 + 0 > ql) sv.x = -1e30f;
                if (tx * 4 + 1 > ql) sv.y = -1e30f;
                if (tx * 4 + 2 > ql) sv.z = -1e30f;
                if (tx * 4 + 3 > ql) sv.w = -1e30f;
            }
            *(float4*)(&sS[(ty * 4 + i) * 256 + kt * 64 + tx * 4]) = sv;
        }
        __syncthreads();
    }

    // ---------------- Softmax (unnormalized exp + row sums) ----------------
    const int nk = (qt + 1) * 64;
    {
        int r = tid >> 2;
        int p = tid & 3;
        int chunk = nk >> 2;
        float* row = sS + r * 256 + p * chunk;
        float m = -3.4e38f;
        for (int t = 0; t < chunk; ++t) m = fmaxf(m, row[t]);
        redm[r * 4 + p] = m;
        __syncthreads();
        float mm = fmaxf(fmaxf(redm[r * 4], redm[r * 4 + 1]),
                         fmaxf(redm[r * 4 + 2], redm[r * 4 + 3]));
        float s = 0.f;
        for (int t = 0; t < chunk; ++t) {
            float e = __expf(row[t] - mm);
            row[t] = e;
            s += e;
        }
        reds[r * 4 + p] = s;
        __syncthreads();
        if (p == 0)
            rsum[r] = reds[r * 4] + reds[r * 4 + 1] + reds[r * 4 + 2] + reds[r * 4 + 3];
        __syncthreads();
    }

    // ---------------- Phase 2: O = P V ----------------
    unsigned long long accO[4][2];   // [q 0..3][h-pair 0..1]
    #pragma unroll
    for (int i = 0; i < 4; ++i) { accO[i][0] = 0ull; accO[i][1] = 0ull; }

    for (int kt = 0; kt <= qt; ++kt) {
        const float* __restrict__ Vg = g_V + ((size_t)b * SEQ + kt * 64) * HEAD;
        // Load V tile natural layout: sKV[k*68 + h]
        for (int idx = tid; idx < 1024; idx += 256) {
            int k  = idx >> 4;
            int hq = idx & 15;
            float4 v = *(const float4*)(Vg + (size_t)k * HEAD + hq * 4);
            *(float4*)(&sKV[k * 68 + hq * 4]) = v;
        }
        __syncthreads();

        const float* pbase = sS + kt * 64;
        #pragma unroll 4
        for (int k = 0; k < 64; ++k) {
            unsigned long long p0 = pack2(pbase[(ty * 4 + 0) * 256 + k]);
            unsigned long long p1 = pack2(pbase[(ty * 4 + 1) * 256 + k]);
            unsigned long long p2 = pack2(pbase[(ty * 4 + 2) * 256 + k]);
            unsigned long long p3 = pack2(pbase[(ty * 4 + 3) * 256 + k]);
            ulonglong2 v01 = *(const ulonglong2*)(&sKV[k * 68 + tx * 4]);  // (h0,h1),(h2,h3)
            fma2(accO[0][0], p0, v01.x); fma2(accO[0][1], p0, v01.y);
            fma2(accO[1][0], p1, v01.x); fma2(accO[1][1], p1, v01.y);
            fma2(accO[2][0], p2, v01.x); fma2(accO[2][1], p2, v01.y);
            fma2(accO[3][0], p3, v01.x); fma2(accO[3][1], p3, v01.y);
        }
        __syncthreads();
    }

    // Epilogue: normalize and store
    #pragma unroll
    for (int i = 0; i < 4; ++i) {
        int q = ty * 4 + i;
        float inv = 1.0f / rsum[q];
        F2U u0, u1; u0.u = accO[i][0]; u1.u = accO[i][1];
        float4 o = make_float4(u0.f.x * inv, u0.f.y * inv, u1.f.x * inv, u1.f.y * inv);
        *(float4*)(outp + ((size_t)b * SEQ + r0 + q) * HEAD + tx * 4) = o;
    }
}

// ---------------------------------------------------------------------------
extern "C" void kernel_launch(void* const* d_in, const int* in_sizes, int n_in,
                              void* d_out, int out_size) {
    const float* x  = (const float*)d_in[0];
    const float* Wq = (const float*)d_in[1];
    const float* bq = (const float*)d_in[2];
    const float* Wk = (const float*)d_in[3];
    const float* bk = (const float*)d_in[4];
    const float* Wv = (const float*)d_in[5];
    const float* bv = (const float*)d_in[6];
    float* out = (float*)d_out;

    qkv_kernel<<<dim3((BATCH * SEQ) / 128, 3), 256>>>(x, Wq, bq, Wk, bk, Wv, bv);

    cudaFuncSetAttribute(attn_kernel, cudaFuncAttributeMaxDynamicSharedMemorySize,
                         ATTN_SMEM_BYTES);
    attn_kernel<<<dim3(4, BATCH), 256, ATTN_SMEM_BYTES>>>(out);
}

// round 7
// speedup vs baseline: 1.8606x; 1.8606x over previous
#include <cuda_runtime.h>
#include <cuda_bf16.h>
#include <cstdint>

// Problem constants
#define BATCH 512
#define SEQ   256
#define CEMB  384
#define HEAD  64
#define SCALE 0.125f   // 64^-0.5
#define QKV_N 192      // Q|K|V fused N
#define KC    32       // K-chunk
#define NKCHUNK (CEMB / KC)   // 12

// Device-global scratch (allowed)
__device__ float g_QKV[(size_t)BATCH * SEQ * QKV_N];   // [m][192] : Q|K|V
__device__ float g_WB[(size_t)CEMB * QKV_N];           // [k][n] fused weights (tf32)
__device__ float g_bias[QKV_N];

// ---------------------------------------------------------------------------
// helpers
// ---------------------------------------------------------------------------
__device__ __forceinline__ float tf32r(float x) {
    uint32_t u;
    asm("cvt.rna.tf32.f32 %0, %1;" : "=r"(u) : "f"(x));
    return __uint_as_float(u);
}

// m16n8k8 tf32 HMMA (sm_80+ portable path — compiles for sm_103)
__device__ __forceinline__ void mma_tf32(float* d, const uint32_t* a, const uint32_t* b) {
    asm volatile("mma.sync.aligned.m16n8k8.row.col.f32.tf32.tf32.f32 "
        "{%0,%1,%2,%3}, {%4,%5,%6,%7}, {%8,%9}, {%0,%1,%2,%3};"
        : "+f"(d[0]), "+f"(d[1]), "+f"(d[2]), "+f"(d[3])
        : "r"(a[0]), "r"(a[1]), "r"(a[2]), "r"(a[3]), "r"(b[0]), "r"(b[1]));
}

// packed f32x2 helpers (attention kernel)
__device__ __forceinline__ void fma2(unsigned long long& d,
                                     unsigned long long a, unsigned long long b) {
    asm("fma.rn.f32x2 %0, %1, %2, %0;" : "+l"(d) : "l"(a), "l"(b));
}
__device__ __forceinline__ unsigned long long pack2(float v) {
    unsigned long long r;
    asm("mov.b64 %0, {%1, %1};" : "=l"(r) : "f"(v));
    return r;
}
union F2U { unsigned long long u; float2 f; };

// ---------------------------------------------------------------------------
// Prep: pack Wq|Wk|Wv -> g_WB [384][192] (tf32-rounded), fuse biases
// ---------------------------------------------------------------------------
__global__ void prep_kernel(const float* __restrict__ Wq, const float* __restrict__ bq,
                            const float* __restrict__ Wk, const float* __restrict__ bk,
                            const float* __restrict__ Wv, const float* __restrict__ bv) {
    int i = blockIdx.x * 256 + threadIdx.x;
    if (i < CEMB * QKV_N) {
        int k = i / QKV_N, n = i % QKV_N;
        const float* W = (n < 64) ? Wq : (n < 128) ? Wk : Wv;
        g_WB[i] = tf32r(W[(size_t)k * HEAD + (n & 63)]);
    }
    if (i < QKV_N) {
        const float* bb = (i < 64) ? bq : (i < 128) ? bk : bv;
        g_bias[i] = bb[i & 63];
    }
}

// ---------------------------------------------------------------------------
// Kernel 1: fused QKV projection via mma.sync tf32.
//   grid = (1024, 2), 256 threads. CTA tile 128(M) x 96(N), K chunked by 32.
//   Warp grid 4x2 -> warp tile 32x48 = 2x6 m16n8k8 atoms.
// ---------------------------------------------------------------------------
#define SA_STRIDE 34    // [m][k] k-stride (pad 2)
#define SB_STRIDE 104   // [k][n] n-stride (pad 8)

__global__ __launch_bounds__(256)
void qkv_hmma_kernel(const float* __restrict__ x) {
    __shared__ float sA[128 * SA_STRIDE];
    __shared__ float sB[KC * SB_STRIDE];
    __shared__ float sbias[96];

    const int tid  = threadIdx.x;
    const int lane = tid & 31;
    const int wid  = tid >> 5;
    const int gid  = lane >> 2;   // 0..7
    const int tig  = lane & 3;    // 0..3
    const int m0   = blockIdx.x * 128;
    const int nb   = blockIdx.y * 96;      // global col base
    const int wm   = (wid >> 1) * 32;      // warp m offset in tile
    const int wn   = (wid & 1) * 48;       // warp n offset within 96

    if (tid < 96) sbias[tid] = g_bias[nb + tid];

    float acc[2][6][4];
    #pragma unroll
    for (int ma = 0; ma < 2; ++ma)
        #pragma unroll
        for (int na = 0; na < 6; ++na)
            #pragma unroll
            for (int j = 0; j < 4; ++j) acc[ma][na][j] = 0.f;

    for (int c = 0; c < NKCHUNK; ++c) {
        __syncthreads();
        // A tile: 128 rows x 32 k (1024 float4, 4 per thread), tf32-rounded
        #pragma unroll
        for (int it = 0; it < 4; ++it) {
            int idx = tid + it * 256;
            int row = idx >> 3, k4 = (idx & 7) * 4;
            float4 v = *(const float4*)(x + (size_t)(m0 + row) * CEMB + c * KC + k4);
            float* d = &sA[row * SA_STRIDE + k4];
            d[0] = tf32r(v.x); d[1] = tf32r(v.y); d[2] = tf32r(v.z); d[3] = tf32r(v.w);
        }
        // B tile: 32 k-rows x 96 n (768 float4, 3 per thread)
        {
            int krow = tid >> 3, seg = tid & 7;
            #pragma unroll
            for (int p = 0; p < 3; ++p) {
                int col = (seg + p * 8) * 4;
                float4 v = *(const float4*)(g_WB + (size_t)(c * KC + krow) * QKV_N + nb + col);
                float* d = &sB[krow * SB_STRIDE + col];
                d[0] = tf32r(v.x); d[1] = tf32r(v.y); d[2] = tf32r(v.z); d[3] = tf32r(v.w);
            }
        }
        __syncthreads();

        #pragma unroll
        for (int ks = 0; ks < 4; ++ks) {
            const int k0 = ks * 8;
            uint32_t a[2][4], b[6][2];
            #pragma unroll
            for (int ma = 0; ma < 2; ++ma) {
                const float* ap = &sA[(wm + ma * 16 + gid) * SA_STRIDE + k0];
                a[ma][0] = __float_as_uint(ap[tig]);
                a[ma][1] = __float_as_uint(ap[8 * SA_STRIDE + tig]);
                a[ma][2] = __float_as_uint(ap[tig + 4]);
                a[ma][3] = __float_as_uint(ap[8 * SA_STRIDE + tig + 4]);
            }
            #pragma unroll
            for (int na = 0; na < 6; ++na) {
                const float* bp = &sB[(k0 + tig) * SB_STRIDE + wn + na * 8 + gid];
                b[na][0] = __float_as_uint(bp[0]);
                b[na][1] = __float_as_uint(bp[4 * SB_STRIDE]);
            }
            #pragma unroll
            for (int ma = 0; ma < 2; ++ma)
                #pragma unroll
                for (int na = 0; na < 6; ++na)
                    mma_tf32(acc[ma][na], a[ma], b[na]);
        }
    }

    // Epilogue: bias + store (C frag cols 2*tig, 2*tig+1 contiguous -> STG.64)
    #pragma unroll
    for (int ma = 0; ma < 2; ++ma) {
        int r0 = m0 + wm + ma * 16 + gid;
        #pragma unroll
        for (int na = 0; na < 6; ++na) {
            int lc = wn + na * 8 + 2 * tig;
            float2 v0 = make_float2(acc[ma][na][0] + sbias[lc],
                                    acc[ma][na][1] + sbias[lc + 1]);
            float2 v1 = make_float2(acc[ma][na][2] + sbias[lc],
                                    acc[ma][na][3] + sbias[lc + 1]);
            *(float2*)(g_QKV + (size_t)r0 * QKV_N + nb + lc)       = v0;
            *(float2*)(g_QKV + (size_t)(r0 + 8) * QKV_N + nb + lc) = v1;
        }
    }
}

// ---------------------------------------------------------------------------
// Kernel 2: causal attention per (batch, 64-query tile). (R4-passing version;
// Q/K/V read from fused g_QKV with row stride 192)
// ---------------------------------------------------------------------------
#define ATTN_SMEM_FLOATS (8448 + 4352 + 16384 + 256 + 256 + 64)
#define ATTN_SMEM_BYTES  (ATTN_SMEM_FLOATS * 4)

__global__ __launch_bounds__(256)
void attn_kernel(float* __restrict__ outp) {
    extern __shared__ float sm[];
    float* sQ   = sm;               // [h][2q] duplicated
    float* sKV  = sQ + 8448;        // phase1: [h][k] (K^T) ; phase2: [k][h] (V)
    float* sS   = sKV + 4352;       // [q][256]
    float* redm = sS + 16384;
    float* reds = redm + 256;
    float* rsum = reds + 256;

    const int tid = threadIdx.x;
    const int ty = tid >> 4;
    const int tx = tid & 15;
    const int b  = blockIdx.y;
    const int qt = blockIdx.x;
    const int r0 = qt * 64;

    const float* __restrict__ Qg = g_QKV + ((size_t)b * SEQ + r0) * QKV_N;

    for (int idx = tid; idx < 1024; idx += 256) {
        int q  = idx >> 4;
        int hq = idx & 15;
        float4 v = *(const float4*)(Qg + (size_t)q * QKV_N + hq * 4);
        float vv[4] = {v.x * SCALE, v.y * SCALE, v.z * SCALE, v.w * SCALE};
        #pragma unroll
        for (int u = 0; u < 4; ++u) {
            int h = hq * 4 + u;
            sQ[h * 132 + 2 * q]     = vv[u];
            sQ[h * 132 + 2 * q + 1] = vv[u];
        }
    }
    __syncthreads();

    // Phase 1: scores
    for (int kt = 0; kt <= qt; ++kt) {
        const float* __restrict__ Kg = g_QKV + ((size_t)b * SEQ + kt * 64) * QKV_N + 64;
        for (int idx = tid; idx < 1024; idx += 256) {
            int k  = idx >> 4;
            int hq = idx & 15;
            float4 v = *(const float4*)(Kg + (size_t)k * QKV_N + hq * 4);
            sKV[(hq * 4 + 0) * 68 + k] = v.x;
            sKV[(hq * 4 + 1) * 68 + k] = v.y;
            sKV[(hq * 4 + 2) * 68 + k] = v.z;
            sKV[(hq * 4 + 3) * 68 + k] = v.w;
        }
        __syncthreads();

        unsigned long long accS[4][2];
        #pragma unroll
        for (int i = 0; i < 4; ++i) { accS[i][0] = 0ull; accS[i][1] = 0ull; }

        #pragma unroll 4
        for (int h = 0; h < 64; ++h) {
            ulonglong2 a01 = *(const ulonglong2*)(&sQ[h * 132 + ty * 8]);
            ulonglong2 a23 = *(const ulonglong2*)(&sQ[h * 132 + ty * 8 + 4]);
            ulonglong2 bk  = *(const ulonglong2*)(&sKV[h * 68 + tx * 4]);
            fma2(accS[0][0], a01.x, bk.x); fma2(accS[0][1], a01.x, bk.y);
            fma2(accS[1][0], a01.y, bk.x); fma2(accS[1][1], a01.y, bk.y);
            fma2(accS[2][0], a23.x, bk.x); fma2(accS[2][1], a23.x, bk.y);
            fma2(accS[3][0], a23.y, bk.x); fma2(accS[3][1], a23.y, bk.y);
        }

        #pragma unroll
        for (int i = 0; i < 4; ++i) {
            F2U u0, u1; u0.u = accS[i][0]; u1.u = accS[i][1];
            float4 sv = make_float4(u0.f.x, u0.f.y, u1.f.x, u1.f.y);
            if (kt == qt) {
                int ql = ty * 4 + i;
                if (tx * 4 + 0 > ql) sv.x = -1e30f;
                if (tx * 4 + 1 > ql) sv.y = -1e30f;
                if (tx * 4 + 2 > ql) sv.z = -1e30f;
                if (tx * 4 + 3 > ql) sv.w = -1e30f;
            }
            *(float4*)(&sS[(ty * 4 + i) * 256 + kt * 64 + tx * 4]) = sv;
        }
        __syncthreads();
    }

    // Softmax (unnormalized exp + row sums)
    const int nk = (qt + 1) * 64;
    {
        int r = tid >> 2;
        int p = tid & 3;
        int chunk = nk >> 2;
        float* row = sS + r * 256 + p * chunk;
        float m = -3.4e38f;
        for (int t = 0; t < chunk; ++t) m = fmaxf(m, row[t]);
        redm[r * 4 + p] = m;
        __syncthreads();
        float mm = fmaxf(fmaxf(redm[r * 4], redm[r * 4 + 1]),
                         fmaxf(redm[r * 4 + 2], redm[r * 4 + 3]));
        float s = 0.f;
        for (int t = 0; t < chunk; ++t) {
            float e = __expf(row[t] - mm);
            row[t] = e;
            s += e;
        }
        reds[r * 4 + p] = s;
        __syncthreads();
        if (p == 0)
            rsum[r] = reds[r * 4] + reds[r * 4 + 1] + reds[r * 4 + 2] + reds[r * 4 + 3];
        __syncthreads();
    }

    // Phase 2: O = P V
    unsigned long long accO[4][2];
    #pragma unroll
    for (int i = 0; i < 4; ++i) { accO[i][0] = 0ull; accO[i][1] = 0ull; }

    for (int kt = 0; kt <= qt; ++kt) {
        const float* __restrict__ Vg = g_QKV + ((size_t)b * SEQ + kt * 64) * QKV_N + 128;
        for (int idx = tid; idx < 1024; idx += 256) {
            int k  = idx >> 4;
            int hq = idx & 15;
            float4 v = *(const float4*)(Vg + (size_t)k * QKV_N + hq * 4);
            *(float4*)(&sKV[k * 68 + hq * 4]) = v;
        }
        __syncthreads();

        const float* pbase = sS + kt * 64;
        #pragma unroll 4
        for (int k = 0; k < 64; ++k) {
            unsigned long long p0 = pack2(pbase[(ty * 4 + 0) * 256 + k]);
            unsigned long long p1 = pack2(pbase[(ty * 4 + 1) * 256 + k]);
            unsigned long long p2 = pack2(pbase[(ty * 4 + 2) * 256 + k]);
            unsigned long long p3 = pack2(pbase[(ty * 4 + 3) * 256 + k]);
            ulonglong2 v01 = *(const ulonglong2*)(&sKV[k * 68 + tx * 4]);
            fma2(accO[0][0], p0, v01.x); fma2(accO[0][1], p0, v01.y);
            fma2(accO[1][0], p1, v01.x); fma2(accO[1][1], p1, v01.y);
            fma2(accO[2][0], p2, v01.x); fma2(accO[2][1], p2, v01.y);
            fma2(accO[3][0], p3, v01.x); fma2(accO[3][1], p3, v01.y);
        }
        __syncthreads();
    }

    #pragma unroll
    for (int i = 0; i < 4; ++i) {
        int q = ty * 4 + i;
        float inv = 1.0f / rsum[q];
        F2U u0, u1; u0.u = accO[i][0]; u1.u = accO[i][1];
        float4 o = make_float4(u0.f.x * inv, u0.f.y * inv, u1.f.x * inv, u1.f.y * inv);
        *(float4*)(outp + ((size_t)b * SEQ + r0 + q) * HEAD + tx * 4) = o;
    }
}

// ---------------------------------------------------------------------------
extern "C" void kernel_launch(void* const* d_in, const int* in_sizes, int n_in,
                              void* d_out, int out_size) {
    const float* x  = (const float*)d_in[0];
    const float* Wq = (const float*)d_in[1];
    const float* bq = (const float*)d_in[2];
    const float* Wk = (const float*)d_in[3];
    const float* bk = (const float*)d_in[4];
    const float* Wv = (const float*)d_in[5];
    const float* bv = (const float*)d_in[6];
    float* out = (float*)d_out;

    prep_kernel<<<(CEMB * QKV_N + 255) / 256, 256>>>(Wq, bq, Wk, bk, Wv, bv);

    qkv_hmma_kernel<<<dim3((BATCH * SEQ) / 128, 2), 256>>>(x);

    cudaFuncSetAttribute(attn_kernel, cudaFuncAttributeMaxDynamicSharedMemorySize,
                         ATTN_SMEM_BYTES);
    attn_kernel<<<dim3(4, BATCH), 256, ATTN_SMEM_BYTES>>>(out);
}

// round 8
// speedup vs baseline: 3.7420x; 2.0112x over previous
#include <cuda_runtime.h>
#include <cuda_bf16.h>
#include <cstdint>

// Problem constants
#define BATCH 512
#define SEQ   256
#define CEMB  384
#define HEAD  64
#define SCALE 0.125f   // 64^-0.5
#define QKV_N 192      // Q|K|V fused N
#define KC    32       // K-chunk
#define NKCHUNK (CEMB / KC)   // 12

// Device-global scratch (allowed)
__device__ float g_QKV[(size_t)BATCH * SEQ * QKV_N];   // [m][192] : Q|K (V region unused)
__device__ float g_VT[(size_t)BATCH * HEAD * SEQ];     // [b][h][seq] : V transposed
__device__ float g_WB[(size_t)CEMB * QKV_N];           // [k][n] fused weights (tf32)
__device__ float g_bias[QKV_N];

// ---------------------------------------------------------------------------
// helpers
// ---------------------------------------------------------------------------
__device__ __forceinline__ float tf32r(float x) {
    uint32_t u;
    asm("cvt.rna.tf32.f32 %0, %1;" : "=r"(u) : "f"(x));
    return __uint_as_float(u);
}

// m16n8k8 tf32 HMMA (sm_80+ portable path)
__device__ __forceinline__ void mma_tf32(float* d, const uint32_t* a, const uint32_t* b) {
    asm volatile("mma.sync.aligned.m16n8k8.row.col.f32.tf32.tf32.f32 "
        "{%0,%1,%2,%3}, {%4,%5,%6,%7}, {%8,%9}, {%0,%1,%2,%3};"
        : "+f"(d[0]), "+f"(d[1]), "+f"(d[2]), "+f"(d[3])
        : "r"(a[0]), "r"(a[1]), "r"(a[2]), "r"(a[3]), "r"(b[0]), "r"(b[1]));
}

// ---------------------------------------------------------------------------
// Prep: pack Wq|Wk|Wv -> g_WB [384][192] (tf32-rounded), fuse biases
// ---------------------------------------------------------------------------
__global__ void prep_kernel(const float* __restrict__ Wq, const float* __restrict__ bq,
                            const float* __restrict__ Wk, const float* __restrict__ bk,
                            const float* __restrict__ Wv, const float* __restrict__ bv) {
    int i = blockIdx.x * 256 + threadIdx.x;
    if (i < CEMB * QKV_N) {
        int k = i / QKV_N, n = i % QKV_N;
        const float* W = (n < 64) ? Wq : (n < 128) ? Wk : Wv;
        g_WB[i] = tf32r(W[(size_t)k * HEAD + (n & 63)]);
    }
    if (i < QKV_N) {
        const float* bb = (i < 64) ? bq : (i < 128) ? bk : bv;
        g_bias[i] = bb[i & 63];
    }
}

// ---------------------------------------------------------------------------
// Kernel 1: fused QKV projection via mma.sync tf32.
//   grid = (1024, 2), 256 threads. CTA tile 128(M) x 96(N), K chunked by 32.
//   Warp grid 4x2 -> warp tile 32x48 = 2x6 m16n8k8 atoms.
//   Epilogue: Q,K cols (<128) -> g_QKV rows; V cols (>=128) -> g_VT transposed.
// ---------------------------------------------------------------------------
#define SA_STRIDE 34    // [m][k] k-stride (pad 2)
#define SB_STRIDE 104   // [k][n] n-stride (pad 8)

__global__ __launch_bounds__(256)
void qkv_hmma_kernel(const float* __restrict__ x) {
    __shared__ float sA[128 * SA_STRIDE];
    __shared__ float sB[KC * SB_STRIDE];
    __shared__ float sbias[96];

    const int tid  = threadIdx.x;
    const int lane = tid & 31;
    const int wid  = tid >> 5;
    const int gid  = lane >> 2;   // 0..7
    const int tig  = lane & 3;    // 0..3
    const int m0   = blockIdx.x * 128;
    const int nb   = blockIdx.y * 96;      // global col base
    const int wm   = (wid >> 1) * 32;      // warp m offset in tile
    const int wn   = (wid & 1) * 48;       // warp n offset within 96

    if (tid < 96) sbias[tid] = g_bias[nb + tid];

    float acc[2][6][4];
    #pragma unroll
    for (int ma = 0; ma < 2; ++ma)
        #pragma unroll
        for (int na = 0; na < 6; ++na)
            #pragma unroll
            for (int j = 0; j < 4; ++j) acc[ma][na][j] = 0.f;

    for (int c = 0; c < NKCHUNK; ++c) {
        __syncthreads();
        // A tile: 128 rows x 32 k (1024 float4, 4 per thread), tf32-rounded
        #pragma unroll
        for (int it = 0; it < 4; ++it) {
            int idx = tid + it * 256;
            int row = idx >> 3, k4 = (idx & 7) * 4;
            float4 v = *(const float4*)(x + (size_t)(m0 + row) * CEMB + c * KC + k4);
            float* d = &sA[row * SA_STRIDE + k4];
            d[0] = tf32r(v.x); d[1] = tf32r(v.y); d[2] = tf32r(v.z); d[3] = tf32r(v.w);
        }
        // B tile: 32 k-rows x 96 n (768 float4, 3 per thread), already tf32
        {
            int krow = tid >> 3, seg = tid & 7;
            #pragma unroll
            for (int p = 0; p < 3; ++p) {
                int col = (seg + p * 8) * 4;
                float4 v = *(const float4*)(g_WB + (size_t)(c * KC + krow) * QKV_N + nb + col);
                float* d = &sB[krow * SB_STRIDE + col];
                d[0] = v.x; d[1] = v.y; d[2] = v.z; d[3] = v.w;
            }
        }
        __syncthreads();

        #pragma unroll
        for (int ks = 0; ks < 4; ++ks) {
            const int k0 = ks * 8;
            uint32_t a[2][4], b[6][2];
            #pragma unroll
            for (int ma = 0; ma < 2; ++ma) {
                const float* ap = &sA[(wm + ma * 16 + gid) * SA_STRIDE + k0];
                a[ma][0] = __float_as_uint(ap[tig]);
                a[ma][1] = __float_as_uint(ap[8 * SA_STRIDE + tig]);
                a[ma][2] = __float_as_uint(ap[tig + 4]);
                a[ma][3] = __float_as_uint(ap[8 * SA_STRIDE + tig + 4]);
            }
            #pragma unroll
            for (int na = 0; na < 6; ++na) {
                const float* bp = &sB[(k0 + tig) * SB_STRIDE + wn + na * 8 + gid];
                b[na][0] = __float_as_uint(bp[0]);
                b[na][1] = __float_as_uint(bp[4 * SB_STRIDE]);
            }
            #pragma unroll
            for (int ma = 0; ma < 2; ++ma)
                #pragma unroll
                for (int na = 0; na < 6; ++na)
                    mma_tf32(acc[ma][na], a[ma], b[na]);
        }
    }

    // Epilogue: bias + store.  Q,K -> g_QKV rows; V -> g_VT [b][h][seq]
    #pragma unroll
    for (int ma = 0; ma < 2; ++ma) {
        int r  = m0 + wm + ma * 16 + gid;
        int bb = r >> 8;          // batch (tile never crosses a 256 boundary)
        int sq = r & 255;         // seq within batch
        #pragma unroll
        for (int na = 0; na < 6; ++na) {
            int lc = wn + na * 8 + 2 * tig;
            int cg = nb + lc;
            float v0 = acc[ma][na][0] + sbias[lc];
            float v1 = acc[ma][na][1] + sbias[lc + 1];
            float v2 = acc[ma][na][2] + sbias[lc];
            float v3 = acc[ma][na][3] + sbias[lc + 1];
            if (cg < 128) {   // uniform per (warp, na): 8-col atom never straddles 128
                *(float2*)(g_QKV + (size_t)r * QKV_N + cg)       = make_float2(v0, v1);
                *(float2*)(g_QKV + (size_t)(r + 8) * QKV_N + cg) = make_float2(v2, v3);
            } else {
                float* vt = g_VT + ((size_t)bb * HEAD + (cg - 128)) * SEQ + sq;
                vt[0]       = v0;   // (h, seq)
                vt[SEQ]     = v1;   // (h+1, seq)
                vt[8]       = v2;   // (h, seq+8)
                vt[SEQ + 8] = v3;   // (h+1, seq+8)
            }
        }
    }
}

// ---------------------------------------------------------------------------
// Kernel 2: causal attention per (batch, 64-query tile) via mma.sync tf32.
//   grid = (4, 512), 256 threads (8 warps, 4x2 warp grid; warp tile 16x32).
//   Phase 1: S = (Q*SCALE)K^T  (K natural layout = col-major B, no transpose)
//   Softmax: unnormalized exp + deferred divide
//   Phase 2: O = P V  using pre-transposed g_VT
// SMEM floats: sQ 64*68 | sKV 64*68 | sS 64*258 | redm 256 | reds 256 | rsum 64
// ---------------------------------------------------------------------------
#define SS_STRIDE 258
#define ATTN_SMEM_FLOATS (64*68 + 64*68 + 64*SS_STRIDE + 256 + 256 + 64)
#define ATTN_SMEM_BYTES  (ATTN_SMEM_FLOATS * 4)

__global__ __launch_bounds__(256)
void attn_kernel(float* __restrict__ outp) {
    extern __shared__ float sm[];
    float* sQ   = sm;                       // [64][68]  Q (scaled, tf32)
    float* sKV  = sQ + 64 * 68;             // [64][68]  K[seq][h]  /  V^T[h][seq]
    float* sS   = sKV + 64 * 68;            // [64][258] scores / probs
    float* redm = sS + 64 * SS_STRIDE;
    float* reds = redm + 256;
    float* rsum = reds + 256;

    const int tid  = threadIdx.x;
    const int lane = tid & 31;
    const int wid  = tid >> 5;
    const int gid  = lane >> 2;
    const int tig  = lane & 3;
    const int wm   = (wid >> 1) * 16;       // warp row group (0,16,32,48)
    const int wn   = (wid & 1) * 32;        // warp col half  (0,32)
    const int b    = blockIdx.y;
    const int qt   = blockIdx.x;
    const int r0   = qt * 64;

    // Load Q tile (scaled, tf32-rounded), natural [q][h]
    {
        const float* Qg = g_QKV + ((size_t)b * SEQ + r0) * QKV_N;
        #pragma unroll
        for (int it = 0; it < 4; ++it) {
            int idx = tid + it * 256;
            int q = idx >> 4, h4 = (idx & 15) * 4;
            float4 v = *(const float4*)(Qg + (size_t)q * QKV_N + h4);
            float* d = &sQ[q * 68 + h4];
            d[0] = tf32r(v.x * SCALE); d[1] = tf32r(v.y * SCALE);
            d[2] = tf32r(v.z * SCALE); d[3] = tf32r(v.w * SCALE);
        }
    }

    // ---------------- Phase 1: S = Q K^T ----------------
    for (int kt = 0; kt <= qt; ++kt) {
        const float* Kg = g_QKV + ((size_t)b * SEQ + kt * 64) * QKV_N + 64;
        #pragma unroll
        for (int it = 0; it < 4; ++it) {
            int idx = tid + it * 256;
            int s = idx >> 4, h4 = (idx & 15) * 4;
            float4 v = *(const float4*)(Kg + (size_t)s * QKV_N + h4);
            float* d = &sKV[s * 68 + h4];
            d[0] = tf32r(v.x); d[1] = tf32r(v.y); d[2] = tf32r(v.z); d[3] = tf32r(v.w);
        }
        __syncthreads();

        float accS[4][4];
        #pragma unroll
        for (int na = 0; na < 4; ++na)
            #pragma unroll
            for (int j = 0; j < 4; ++j) accS[na][j] = 0.f;

        #pragma unroll
        for (int ks = 0; ks < 8; ++ks) {
            const int k0 = ks * 8;
            uint32_t a[4];
            const float* ap = &sQ[(wm + gid) * 68 + k0];
            a[0] = __float_as_uint(ap[tig]);
            a[1] = __float_as_uint(ap[8 * 68 + tig]);
            a[2] = __float_as_uint(ap[tig + 4]);
            a[3] = __float_as_uint(ap[8 * 68 + tig + 4]);
            #pragma unroll
            for (int na = 0; na < 4; ++na) {
                const float* bp = &sKV[(wn + na * 8 + gid) * 68 + k0];
                uint32_t bb2[2] = { __float_as_uint(bp[tig]), __float_as_uint(bp[tig + 4]) };
                mma_tf32(accS[na], a, bb2);
            }
        }

        // store S (mask on diagonal tile)
        #pragma unroll
        for (int na = 0; na < 4; ++na) {
            int q0 = wm + gid;
            int cl = wn + na * 8 + 2 * tig;     // local key col
            float2 v0 = make_float2(accS[na][0], accS[na][1]);
            float2 v1 = make_float2(accS[na][2], accS[na][3]);
            if (kt == qt) {
                if (cl     > q0)     v0.x = -1e30f;
                if (cl + 1 > q0)     v0.y = -1e30f;
                if (cl     > q0 + 8) v1.x = -1e30f;
                if (cl + 1 > q0 + 8) v1.y = -1e30f;
            }
            *(float2*)(&sS[q0 * SS_STRIDE + kt * 64 + cl])       = v0;
            *(float2*)(&sS[(q0 + 8) * SS_STRIDE + kt * 64 + cl]) = v1;
        }
        __syncthreads();
    }

    // ---------------- Softmax (unnormalized exp + row sums) ----------------
    const int nk = (qt + 1) * 64;
    {
        int r = tid >> 2;
        int p = tid & 3;
        int chunk = nk >> 2;
        float* row = sS + r * SS_STRIDE + p * chunk;
        float m = -3.4e38f;
        for (int t = 0; t < chunk; ++t) m = fmaxf(m, row[t]);
        redm[r * 4 + p] = m;
        __syncthreads();
        float mm = fmaxf(fmaxf(redm[r * 4], redm[r * 4 + 1]),
                         fmaxf(redm[r * 4 + 2], redm[r * 4 + 3]));
        float s = 0.f;
        for (int t = 0; t < chunk; ++t) {
            float e = __expf(row[t] - mm);
            row[t] = e;
            s += e;
        }
        reds[r * 4 + p] = s;
        __syncthreads();
        if (p == 0)
            rsum[r] = reds[r * 4] + reds[r * 4 + 1] + reds[r * 4 + 2] + reds[r * 4 + 3];
        __syncthreads();
    }

    // ---------------- Phase 2: O = P V ----------------
    float accO[4][4];
    #pragma unroll
    for (int na = 0; na < 4; ++na)
        #pragma unroll
        for (int j = 0; j < 4; ++j) accO[na][j] = 0.f;

    const float* VTg = g_VT + (size_t)b * HEAD * SEQ;
    for (int kt = 0; kt <= qt; ++kt) {
        // V^T tile: sKV[h][seq-in-tile], coalesced load, conflict-free store
        #pragma unroll
        for (int it = 0; it < 4; ++it) {
            int idx = tid + it * 256;
            int h = idx >> 4, s4 = (idx & 15) * 4;
            float4 v = *(const float4*)(VTg + (size_t)h * SEQ + kt * 64 + s4);
            float* d = &sKV[h * 68 + s4];
            d[0] = tf32r(v.x); d[1] = tf32r(v.y); d[2] = tf32r(v.z); d[3] = tf32r(v.w);
        }
        __syncthreads();

        #pragma unroll
        for (int ks = 0; ks < 8; ++ks) {
            const int k0 = ks * 8;
            const float* pp = &sS[(wm + gid) * SS_STRIDE + kt * 64 + k0];
            uint32_t a[4];
            a[0] = __float_as_uint(tf32r(pp[tig]));
            a[1] = __float_as_uint(tf32r(pp[8 * SS_STRIDE + tig]));
            a[2] = __float_as_uint(tf32r(pp[tig + 4]));
            a[3] = __float_as_uint(tf32r(pp[8 * SS_STRIDE + tig + 4]));
            #pragma unroll
            for (int na = 0; na < 4; ++na) {
                const float* bp = &sKV[(wn + na * 8 + gid) * 68 + k0];
                uint32_t bb2[2] = { __float_as_uint(bp[tig]), __float_as_uint(bp[tig + 4]) };
                mma_tf32(accO[na], a, bb2);
            }
        }
        __syncthreads();
    }

    // Epilogue: normalize, store
    {
        float inv0 = 1.0f / rsum[wm + gid];
        float inv1 = 1.0f / rsum[wm + gid + 8];
        #pragma unroll
        for (int na = 0; na < 4; ++na) {
            int c = wn + na * 8 + 2 * tig;
            float2 o0 = make_float2(accO[na][0] * inv0, accO[na][1] * inv0);
            float2 o1 = make_float2(accO[na][2] * inv1, accO[na][3] * inv1);
            *(float2*)(outp + ((size_t)b * SEQ + r0 + wm + gid) * HEAD + c)     = o0;
            *(float2*)(outp + ((size_t)b * SEQ + r0 + wm + gid + 8) * HEAD + c) = o1;
        }
    }
}

// ---------------------------------------------------------------------------
extern "C" void kernel_launch(void* const* d_in, const int* in_sizes, int n_in,
                              void* d_out, int out_size) {
    const float* x  = (const float*)d_in[0];
    const float* Wq = (const float*)d_in[1];
    const float* bq = (const float*)d_in[2];
    const float* Wk = (const float*)d_in[3];
    const float* bk = (const float*)d_in[4];
    const float* Wv = (const float*)d_in[5];
    const float* bv = (const float*)d_in[6];
    float* out = (float*)d_out;

    prep_kernel<<<(CEMB * QKV_N + 255) / 256, 256>>>(Wq, bq, Wk, bk, Wv, bv);

    qkv_hmma_kernel<<<dim3((BATCH * SEQ) / 128, 2), 256>>>(x);

    cudaFuncSetAttribute(attn_kernel, cudaFuncAttributeMaxDynamicSharedMemorySize,
                         ATTN_SMEM_BYTES);
    attn_kernel<<<dim3(4, BATCH), 256, ATTN_SMEM_BYTES>>>(out);
}

// round 11
// speedup vs baseline: 6.0817x; 1.6252x over previous
#include <cuda_runtime.h>
#include <cuda_fp16.h>
#include <cstdint>

// Problem constants
#define BATCH 512
#define SEQ   256
#define CEMB  384
#define HEAD  64
#define SCALE 0.125f
#define QKV_N 192
#define KC    32
#define NKCHUNK 12

// Device-global scratch (allowed)
__device__ __half g_QK[(size_t)BATCH * SEQ * 128];   // [m][128] : Q(scaled)|K, fp16
__device__ __half g_VT[(size_t)BATCH * HEAD * SEQ];  // [b][h][s] : V transposed, fp16
__device__ __half g_WB[(size_t)QKV_N * CEMB];        // [n][k] fused weights, fp16
__device__ float  g_bias[QKV_N];                     // fused bias (Q part pre-scaled)

// ---------------------------------------------------------------------------
// helpers
// ---------------------------------------------------------------------------
__device__ __forceinline__ uint32_t sptr(const void* p) {
    uint32_t a;
    asm("{ .reg .u64 t; cvta.to.shared.u64 t, %1; cvt.u32.u64 %0, t; }"
        : "=r"(a) : "l"(p));
    return a;
}
__device__ __forceinline__ uint32_t packh2(float x, float y) {
    __half2 h = __floats2half2_rn(x, y);
    return *(uint32_t*)&h;
}
#define LDM_X4(r, addr)                                                         \
    asm volatile("ldmatrix.sync.aligned.m8n8.x4.shared.b16 {%0,%1,%2,%3}, [%4];" \
        : "=r"((r)[0]), "=r"((r)[1]), "=r"((r)[2]), "=r"((r)[3]) : "r"(addr))
#define LDM_X2(r, addr)                                                         \
    asm volatile("ldmatrix.sync.aligned.m8n8.x2.shared.b16 {%0,%1}, [%2];"      \
        : "=r"((r)[0]), "=r"((r)[1]) : "r"(addr))

// m16n8k16 fp16 HMMA, f32 accumulate (sm_80+ portable path)
__device__ __forceinline__ void mma_f16(float* d, const uint32_t* a, const uint32_t* b) {
    asm volatile("mma.sync.aligned.m16n8k16.row.col.f32.f16.f16.f32 "
        "{%0,%1,%2,%3}, {%4,%5,%6,%7}, {%8,%9}, {%0,%1,%2,%3};"
        : "+f"(d[0]), "+f"(d[1]), "+f"(d[2]), "+f"(d[3])
        : "r"(a[0]), "r"(a[1]), "r"(a[2]), "r"(a[3]), "r"(b[0]), "r"(b[1]));
}

// ---------------------------------------------------------------------------
// Prep: Wq|Wk|Wv -> g_WB [n=192][k=384] fp16 (Q part pre-scaled by SCALE)
// ---------------------------------------------------------------------------
__global__ void prep_kernel(const float* __restrict__ Wq, const float* __restrict__ bq,
                            const float* __restrict__ Wk, const float* __restrict__ bk,
                            const float* __restrict__ Wv, const float* __restrict__ bv) {
    int i = blockIdx.x * 256 + threadIdx.x;
    if (i < QKV_N * CEMB) {
        int n = i / CEMB, k = i % CEMB;
        const float* W = (n < 64) ? Wq : (n < 128) ? Wk : Wv;
        float w = W[(size_t)k * HEAD + (n & 63)];
        if (n < 64) w *= SCALE;
        g_WB[i] = __float2half(w);
    }
    if (i < QKV_N) {
        const float* bb = (i < 64) ? bq : (i < 128) ? bk : bv;
        float v = bb[i & 63];
        if (i < 64) v *= SCALE;
        g_bias[i] = v;
    }
}

// ---------------------------------------------------------------------------
// Kernel 1: fused QKV projection, fp16 m16n8k16 + ldmatrix + reg prefetch.
//   grid = (2, 1024): x = N-half (96 cols), y = M tile (128 rows).
//   8 warps 4x2; warp tile 32x48 = 2x6 atoms; KC=32 (2 k-steps of 16).
//   Epilogue: cols<128 -> g_QK fp16 rows; cols>=128 -> g_VT transposed fp16.
// ---------------------------------------------------------------------------
#define SA_STR 40   // halves; 80 B rows (16B-aligned, conflict-free ldmatrix)
#define SB_STR 56   // halves; 112 B rows (16B-aligned, conflict-free ldmatrix)

__global__ __launch_bounds__(256)
void qkv_hmma_kernel(const float* __restrict__ x) {
    __shared__ __half sA[128 * SA_STR];
    __shared__ __half sB[96 * SB_STR];
    __shared__ float sbias[96];

    const int tid  = threadIdx.x;
    const int lane = tid & 31;
    const int wid  = tid >> 5;
    const int gid  = lane >> 2;
    const int tig  = lane & 3;
    const int nb   = blockIdx.x * 96;
    const int m0   = blockIdx.y * 128;
    const int wm   = (wid >> 1) * 32;
    const int wn   = (wid & 1) * 48;

    if (tid < 96) sbias[tid] = g_bias[nb + tid];

    float acc[2][6][4];
    #pragma unroll
    for (int ma = 0; ma < 2; ++ma)
        #pragma unroll
        for (int na = 0; na < 6; ++na)
            #pragma unroll
            for (int j = 0; j < 4; ++j) acc[ma][na][j] = 0.f;

    // prefetch registers
    float4 pa[4];
    uint4  pb0, pb1;
    const int arow = tid >> 3, ak4 = (tid & 7) * 4;        // A: idx=tid+it*256
    const int bn0 = tid >> 2, bs0 = (tid & 3) * 8;         // B slot 0 (rows 0..63)
    const int bn1 = (tid + 256) >> 2, bs1 = (tid & 3) * 8; // B slot 1 (rows 64..95, tid<128)

    // load chunk 0  (FIX: B rows offset by nb)
    #pragma unroll
    for (int it = 0; it < 4; ++it)
        pa[it] = *(const float4*)(x + (size_t)(m0 + arow + it * 32) * CEMB + ak4);
    pb0 = *(const uint4*)(g_WB + (size_t)(nb + bn0) * CEMB + bs0);
    if (tid < 128) pb1 = *(const uint4*)(g_WB + (size_t)(nb + bn1) * CEMB + bs1);

    for (int c = 0; c < NKCHUNK; ++c) {
        // store prefetched chunk to SMEM (f32 -> fp16 for A)
        #pragma unroll
        for (int it = 0; it < 4; ++it) {
            uint2 s;
            s.x = packh2(pa[it].x, pa[it].y);
            s.y = packh2(pa[it].z, pa[it].w);
            *(uint2*)&sA[(arow + it * 32) * SA_STR + ak4] = s;
        }
        *(uint4*)&sB[bn0 * SB_STR + bs0] = pb0;
        if (tid < 128) *(uint4*)&sB[bn1 * SB_STR + bs1] = pb1;
        __syncthreads();

        // prefetch next chunk  (FIX: B rows offset by nb)
        if (c + 1 < NKCHUNK) {
            const int kb = (c + 1) * KC;
            #pragma unroll
            for (int it = 0; it < 4; ++it)
                pa[it] = *(const float4*)(x + (size_t)(m0 + arow + it * 32) * CEMB + kb + ak4);
            pb0 = *(const uint4*)(g_WB + (size_t)(nb + bn0) * CEMB + kb + bs0);
            if (tid < 128) pb1 = *(const uint4*)(g_WB + (size_t)(nb + bn1) * CEMB + kb + bs1);
        }

        // compute: 2 k-steps of 16
        #pragma unroll
        for (int ks = 0; ks < 2; ++ks) {
            const int k0 = ks * 16;
            uint32_t a[2][4];
            #pragma unroll
            for (int ma = 0; ma < 2; ++ma) {
                uint32_t ad = sptr(&sA[(wm + ma * 16 + (lane & 15)) * SA_STR
                                       + k0 + ((lane >> 4) & 1) * 8]);
                LDM_X4(a[ma], ad);
            }
            #pragma unroll
            for (int na = 0; na < 6; ++na) {
                uint32_t b2[2];
                uint32_t bd = sptr(&sB[(wn + na * 8 + (lane & 7)) * SB_STR
                                       + k0 + ((lane >> 3) & 1) * 8]);
                LDM_X2(b2, bd);
                mma_f16(acc[0][na], a[0], b2);
                mma_f16(acc[1][na], a[1], b2);
            }
        }
        __syncthreads();
    }

    // Epilogue: bias; cols<128 -> g_QK, cols>=128 -> g_VT (transposed)
    #pragma unroll
    for (int ma = 0; ma < 2; ++ma) {
        int r  = m0 + wm + ma * 16 + gid;
        int bb = r >> 8;
        int sq = r & 255;
        #pragma unroll
        for (int na = 0; na < 6; ++na) {
            int lc = wn + na * 8 + 2 * tig;
            int cg = nb + lc;
            float v0 = acc[ma][na][0] + sbias[lc];
            float v1 = acc[ma][na][1] + sbias[lc + 1];
            float v2 = acc[ma][na][2] + sbias[lc];
            float v3 = acc[ma][na][3] + sbias[lc + 1];
            if (cg < 128) {   // uniform per (warp,na): 8-col atom never straddles 128
                *(__half2*)(g_QK + (size_t)r * 128 + cg)       = __floats2half2_rn(v0, v1);
                *(__half2*)(g_QK + (size_t)(r + 8) * 128 + cg) = __floats2half2_rn(v2, v3);
            } else {
                __half* vt = g_VT + ((size_t)bb * HEAD + (cg - 128)) * SEQ + sq;
                vt[0]       = __float2half(v0);   // (h,   sq)
                vt[SEQ]     = __float2half(v1);   // (h+1, sq)
                vt[8]       = __float2half(v2);   // (h,   sq+8)
                vt[SEQ + 8] = __float2half(v3);   // (h+1, sq+8)
            }
        }
    }
}

// ---------------------------------------------------------------------------
// Kernel 2: causal attention, fp16 m16n8k16.  grid (4, 512), 256 threads.
//   Phase 1: S = Q K^T (Q pre-scaled).  Softmax f32 (unnormalized).
//   Phase 2: O = P V using pre-transposed g_VT; P cvt f32->h2 at frag load.
// SMEM: sS f32 [64][264] | red 576 f32 | sQ h[64][72] | sKV h[64][72]
// ---------------------------------------------------------------------------
#define SS_STR 264
#define ATTN_SMEM_BYTES ((64 * SS_STR + 576) * 4 + (64 * 72) * 2 * 2)

__global__ __launch_bounds__(256)
void attn_kernel(float* __restrict__ outp) {
    extern __shared__ float sm[];
    float* sS    = sm;                        // [64][264] f32 scores/probs
    float* redm  = sS + 64 * SS_STR;
    float* reds  = redm + 256;
    float* rsum  = reds + 256;
    __half* sQ   = (__half*)(rsum + 64);      // [64][72]
    __half* sKV  = sQ + 64 * 72;              // [64][72]  K[s][h] / V^T[h][s]

    const int tid  = threadIdx.x;
    const int lane = tid & 31;
    const int wid  = tid >> 5;
    const int gid  = lane >> 2;
    const int tig  = lane & 3;
    const int wm   = (wid >> 1) * 16;
    const int wn   = (wid & 1) * 32;
    const int b    = blockIdx.y;
    const int qt   = blockIdx.x;
    const int r0   = qt * 64;

    // Load Q tile (fp16, pre-scaled): [q][h], 512 uint4
    {
        const __half* Qg = g_QK + ((size_t)b * SEQ + r0) * 128;
        #pragma unroll
        for (int it = 0; it < 2; ++it) {
            int idx = tid + it * 256;
            int q = idx >> 3, seg = (idx & 7) * 8;
            *(uint4*)&sQ[q * 72 + seg] = *(const uint4*)(Qg + (size_t)q * 128 + seg);
        }
    }

    // ---------------- Phase 1: S = Q K^T ----------------
    for (int kt = 0; kt <= qt; ++kt) {
        const __half* Kg = g_QK + ((size_t)b * SEQ + kt * 64) * 128 + 64;
        #pragma unroll
        for (int it = 0; it < 2; ++it) {
            int idx = tid + it * 256;
            int s = idx >> 3, seg = (idx & 7) * 8;
            *(uint4*)&sKV[s * 72 + seg] = *(const uint4*)(Kg + (size_t)s * 128 + seg);
        }
        __syncthreads();

        float accS[4][4];
        #pragma unroll
        for (int na = 0; na < 4; ++na)
            #pragma unroll
            for (int j = 0; j < 4; ++j) accS[na][j] = 0.f;

        #pragma unroll
        for (int ks = 0; ks < 4; ++ks) {
            const int k0 = ks * 16;
            uint32_t a[4];
            uint32_t ad = sptr(&sQ[(wm + (lane & 15)) * 72 + k0 + ((lane >> 4) & 1) * 8]);
            LDM_X4(a, ad);
            #pragma unroll
            for (int na = 0; na < 4; ++na) {
                uint32_t b2[2];
                uint32_t bd = sptr(&sKV[(wn + na * 8 + (lane & 7)) * 72
                                        + k0 + ((lane >> 3) & 1) * 8]);
                LDM_X2(b2, bd);
                mma_f16(accS[na], a, b2);
            }
        }

        // store S with causal mask on diagonal tile
        #pragma unroll
        for (int na = 0; na < 4; ++na) {
            int q0 = wm + gid;
            int cl = wn + na * 8 + 2 * tig;
            float2 v0 = make_float2(accS[na][0], accS[na][1]);
            float2 v1 = make_float2(accS[na][2], accS[na][3]);
            if (kt == qt) {
                if (cl     > q0)     v0.x = -1e30f;
                if (cl + 1 > q0)     v0.y = -1e30f;
                if (cl     > q0 + 8) v1.x = -1e30f;
                if (cl + 1 > q0 + 8) v1.y = -1e30f;
            }
            *(float2*)(&sS[q0 * SS_STR + kt * 64 + cl])       = v0;
            *(float2*)(&sS[(q0 + 8) * SS_STR + kt * 64 + cl]) = v1;
        }
        __syncthreads();
    }

    // ---------------- Softmax (f32, unnormalized exp + row sums) ----------------
    const int nk = (qt + 1) * 64;
    {
        int r = tid >> 2;
        int p = tid & 3;
        int chunk = nk >> 2;
        float* row = sS + r * SS_STR + p * chunk;
        float m = -3.4e38f;
        for (int t = 0; t < chunk; ++t) m = fmaxf(m, row[t]);
        redm[r * 4 + p] = m;
        __syncthreads();
        float mm = fmaxf(fmaxf(redm[r * 4], redm[r * 4 + 1]),
                         fmaxf(redm[r * 4 + 2], redm[r * 4 + 3]));
        float s = 0.f;
        for (int t = 0; t < chunk; ++t) {
            float e = __expf(row[t] - mm);
            row[t] = e;
            s += e;
        }
        reds[r * 4 + p] = s;
        __syncthreads();
        if (p == 0)
            rsum[r] = reds[r * 4] + reds[r * 4 + 1] + reds[r * 4 + 2] + reds[r * 4 + 3];
        __syncthreads();
    }

    // ---------------- Phase 2: O = P V ----------------
    float accO[4][4];
    #pragma unroll
    for (int na = 0; na < 4; ++na)
        #pragma unroll
        for (int j = 0; j < 4; ++j) accO[na][j] = 0.f;

    const __half* VTg = g_VT + (size_t)b * HEAD * SEQ;
    for (int kt = 0; kt <= qt; ++kt) {
        // V^T tile: sKV[h][s], coalesced, conflict-free
        #pragma unroll
        for (int it = 0; it < 2; ++it) {
            int idx = tid + it * 256;
            int h = idx >> 3, seg = (idx & 7) * 8;
            *(uint4*)&sKV[h * 72 + seg] = *(const uint4*)(VTg + (size_t)h * SEQ + kt * 64 + seg);
        }
        __syncthreads();

        #pragma unroll
        for (int ks = 0; ks < 4; ++ks) {
            const int k0 = kt * 64 + ks * 16;
            const float* pr0 = &sS[(wm + gid) * SS_STR + k0];
            const float* pr8 = pr0 + 8 * SS_STR;
            float2 f0 = *(const float2*)(pr0 + 2 * tig);
            float2 f1 = *(const float2*)(pr8 + 2 * tig);
            float2 f2 = *(const float2*)(pr0 + 8 + 2 * tig);
            float2 f3 = *(const float2*)(pr8 + 8 + 2 * tig);
            uint32_t a[4] = { packh2(f0.x, f0.y), packh2(f1.x, f1.y),
                              packh2(f2.x, f2.y), packh2(f3.x, f3.y) };
            #pragma unroll
            for (int na = 0; na < 4; ++na) {
                uint32_t b2[2];
                uint32_t bd = sptr(&sKV[(wn + na * 8 + (lane & 7)) * 72
                                        + ks * 16 + ((lane >> 3) & 1) * 8]);
                LDM_X2(b2, bd);
                mma_f16(accO[na], a, b2);
            }
        }
        __syncthreads();
    }

    // Epilogue: normalize, store f32
    {
        float inv0 = 1.0f / rsum[wm + gid];
        float inv1 = 1.0f / rsum[wm + gid + 8];
        #pragma unroll
        for (int na = 0; na < 4; ++na) {
            int c = wn + na * 8 + 2 * tig;
            float2 o0 = make_float2(accO[na][0] * inv0, accO[na][1] * inv0);
            float2 o1 = make_float2(accO[na][2] * inv1, accO[na][3] * inv1);
            *(float2*)(outp + ((size_t)b * SEQ + r0 + wm + gid) * HEAD + c)      = o0;
            *(float2*)(outp + ((size_t)b * SEQ + r0 + wm + gid + 8) * HEAD + c)  = o1;
        }
    }
}

// ---------------------------------------------------------------------------
extern "C" void kernel_launch(void* const* d_in, const int* in_sizes, int n_in,
                              void* d_out, int out_size) {
    const float* x  = (const float*)d_in[0];
    const float* Wq = (const float*)d_in[1];
    const float* bq = (const float*)d_in[2];
    const float* Wk = (const float*)d_in[3];
    const float* bk = (const float*)d_in[4];
    const float* Wv = (const float*)d_in[5];
    const float* bv = (const float*)d_in[6];
    float* out = (float*)d_out;

    prep_kernel<<<(QKV_N * CEMB + 255) / 256, 256>>>(Wq, bq, Wk, bk, Wv, bv);

    qkv_hmma_kernel<<<dim3(2, (BATCH * SEQ) / 128), 256>>>(x);

    cudaFuncSetAttribute(attn_kernel, cudaFuncAttributeMaxDynamicSharedMemorySize,
                         ATTN_SMEM_BYTES);
    attn_kernel<<<dim3(4, BATCH), 256, ATTN_SMEM_BYTES>>>(out);
}